// round 3
// baseline (speedup 1.0000x reference)
#include <cuda_runtime.h>

// Problem constants (fixed by the reference setup_inputs)
#define BB     32
#define NN     4096
#define FDIM   128
#define LDH    200            // L*DH floats per agent in hist_feat
#define KK     8
#define APB    256            // agents per block (== blockDim)
#define CHUNKS 16             // blocks per batch (16*256 = 4096 >= N-1)
#define CANDS  (CHUNKS * KK)  // 128 candidate keys per batch

#define KEY_MAX 0xFFFFFFFFFFFFFFFFull

__device__ unsigned long long g_cand[BB * CANDS];
__device__ int g_counter[BB];   // zero-init; finisher resets to 0 each call

static __device__ __forceinline__ unsigned long long umin64(unsigned long long a,
                                                            unsigned long long b) {
    return a < b ? a : b;
}

// ---------------------------------------------------------------------------
// Fused kernel: per-thread agent scoring + hierarchical top-8 + (last block
// per batch) final merge and gather.
// Keys: (score_bits << 32) | (j-1)  -> min-order = (score asc, index asc),
// matching lax.top_k(-score) tie-break semantics.
// ---------------------------------------------------------------------------
__global__ __launch_bounds__(APB)
void fused_kernel(const float* __restrict__ x,   // (B, N, FDIM)
                  const float* __restrict__ hf,  // (B, N, L, DH)
                  const float* __restrict__ he,  // (B, N, FDIM)
                  unsigned long long* __restrict__ cand,
                  float* __restrict__ out)
{
    const int b     = blockIdx.x / CHUNKS;
    const int chunk = blockIdx.x % CHUNKS;
    const int t     = threadIdx.x;
    const int warp  = t >> 5;
    const int lane  = t & 31;

    __shared__ float4 scx[FDIM / 4];   // center x row
    __shared__ float4 scv[FDIM / 4];   // center embed row
    __shared__ unsigned long long skeys[8 * KK];
    __shared__ int   s_last;
    __shared__ int   sel_idx[KK];

    // stage center rows (broadcast source for all threads)
    if (t < FDIM / 4) {
        scx[t] = ((const float4*)(x  + (size_t)b * NN * FDIM))[t];
        scv[t] = ((const float4*)(he + (size_t)b * NN * FDIM))[t];
    }
    __syncthreads();

    // ---- center direction (uniform loads, every thread computes it) ----
    const float* h0 = hf + (size_t)b * NN * LDH;
    float2 p048 = *(const float2*)(h0 + 192);
    float2 p049 = *(const float2*)(h0 + 196);
    float d0x = p049.x - p048.x, d0y = p049.y - p048.y;
    float inv0 = 1.0f / fmaxf(sqrtf(d0x*d0x + d0y*d0y), 1e-12f);
    float cdx = d0x * inv0 + 1e-8f;
    float cdy = d0y * inv0 + 1e-8f;
    const float cnorm = fmaxf(sqrtf(cdx*cdx + cdy*cdy), 1e-8f);

    // ---- per-thread agent ----
    const int j      = 1 + chunk * APB + t;        // 1 .. 4096
    const bool valid = (j < NN);
    const int js     = valid ? j : 1;              // safe row for loads

    const float4* __restrict__ xr = (const float4*)(x  + ((size_t)b * NN + js) * FDIM);
    const float4* __restrict__ ur = (const float4*)(he + ((size_t)b * NN + js) * FDIM);

    float4 d2a = {0,0,0,0};   // |x_j - c|^2 partials
    float4 tna = {0,0,0,0};   // u . v
    float4 uua = {0,0,0,0};   // |u|^2
    float4 vva = {0,0,0,0};   // |v|^2 (center norm, identical in all threads)

    #pragma unroll 4
    for (int i = 0; i < FDIM / 4; i++) {
        float4 a = xr[i];
        float4 u = ur[i];
        float4 c = scx[i];
        float4 v = scv[i];

        float ex = a.x - c.x, ey = a.y - c.y, ez = a.z - c.z, ew = a.w - c.w;
        d2a.x += ex*ex;  d2a.y += ey*ey;  d2a.z += ez*ez;  d2a.w += ew*ew;
        tna.x += u.x*v.x; tna.y += u.y*v.y; tna.z += u.z*v.z; tna.w += u.w*v.w;
        uua.x += u.x*u.x; uua.y += u.y*u.y; uua.z += u.z*u.z; uua.w += u.w*u.w;
        vva.x += v.x*v.x; vva.y += v.y*v.y; vva.z += v.z*v.z; vva.w += v.w*v.w;
    }

    float d2 = (d2a.x + d2a.y) + (d2a.z + d2a.w);
    float tn = (tna.x + tna.y) + (tna.z + tna.w);
    float uu = (uua.x + uua.y) + (uua.z + uua.w);
    float vv = (vva.x + vva.y) + (vva.z + vva.w);
    const float vnm = fmaxf(sqrtf(vv), 1e-8f);

    // ---- velocity similarity (per-thread hist_feat sectors) ----
    const float* hj = hf + ((size_t)b * NN + js) * LDH;
    float2 a48 = *(const float2*)(hj + 192);
    float2 a49 = *(const float2*)(hj + 196);
    float djx = a49.x - a48.x, djy = a49.y - a48.y;
    float invj = 1.0f / fmaxf(sqrtf(djx*djx + djy*djy), 1e-12f);
    float odx = djx * invj + 1e-8f;
    float ody = djy * invj + 1e-8f;
    float vnum = odx*cdx + ody*cdy;
    float vden = fmaxf(sqrtf(odx*odx + ody*ody), 1e-8f) * cnorm;
    float vsim = vnum / vden;

    float tsim = tn / (fmaxf(sqrtf(uu), 1e-8f) * vnm);
    float score = 0.3f * sqrtf(d2)
                + 0.5f * (1.0f - fmaxf(vsim, 0.0f))
                + 0.4f * (1.0f - fmaxf(tsim, 0.0f));
    score = fmaxf(score, 0.0f);   // keep float bit-pattern order-preserving

    unsigned long long mykey = valid
        ? (((unsigned long long)__float_as_uint(score) << 32) | (unsigned int)(j - 1))
        : KEY_MAX;

    // ---- warp top-8: 8 rounds of 64-bit butterfly argmin ----
    unsigned long long sel = KEY_MAX;
    #pragma unroll
    for (int it = 0; it < KK; it++) {
        unsigned long long m = mykey;
        #pragma unroll
        for (int off = 16; off > 0; off >>= 1)
            m = umin64(m, __shfl_xor_sync(0xffffffffu, m, off));
        if (mykey == m) mykey = KEY_MAX;   // keys unique -> single winner
        if (lane == it) sel = m;
    }
    if (lane < KK) skeys[warp * KK + lane] = sel;
    __syncthreads();

    // ---- block merge: warp 0 reduces 64 -> 8, writes candidates ----
    if (warp == 0) {
        unsigned long long k0 = skeys[lane];
        unsigned long long k1 = skeys[lane + 32];
        unsigned long long sel2 = KEY_MAX;
        #pragma unroll
        for (int it = 0; it < KK; it++) {
            unsigned long long m = umin64(k0, k1);
            #pragma unroll
            for (int off = 16; off > 0; off >>= 1)
                m = umin64(m, __shfl_xor_sync(0xffffffffu, m, off));
            if (k0 == m) k0 = KEY_MAX;
            else if (k1 == m) k1 = KEY_MAX;
            if (lane == it) sel2 = m;
        }
        if (lane < KK)
            cand[((size_t)b * CHUNKS + chunk) * KK + lane] = sel2;
    }

    // ---- arrival protocol: last block of this batch does the final merge ----
    __threadfence();
    __syncthreads();
    if (t == 0) {
        int old = atomicAdd(&g_counter[b], 1);
        s_last = (old == CHUNKS - 1) ? 1 : 0;
    }
    __syncthreads();
    if (!s_last) return;

    __threadfence();   // acquire: see all other blocks' cand writes

    if (t < 32) {
        unsigned long long k[4];
        #pragma unroll
        for (int q = 0; q < 4; q++)
            k[q] = cand[(size_t)b * CANDS + q * 32 + t];

        #pragma unroll
        for (int it = 0; it < KK; it++) {
            unsigned long long m = umin64(umin64(k[0], k[1]), umin64(k[2], k[3]));
            #pragma unroll
            for (int off = 16; off > 0; off >>= 1)
                m = umin64(m, __shfl_xor_sync(0xffffffffu, m, off));
            #pragma unroll
            for (int q = 0; q < 4; q++)
                if (k[q] == m) k[q] = KEY_MAX;
            if (t == 0) sel_idx[it] = (int)(unsigned int)(m & 0xFFFFFFFFu);
        }
        if (t == 0) g_counter[b] = 0;   // reset for next graph replay
    }
    __syncthreads();

    // gather: 256 threads = 8 rows x 32 lanes of float4
    {
        const int kk  = t >> 5;
        const int l   = t & 31;
        const int idx = sel_idx[kk];
        float4 val = ((const float4*)(x + ((size_t)b * NN + idx + 1) * FDIM))[l];
        ((float4*)(out + ((size_t)b * KK + kk) * FDIM))[l] = val;
    }
    if (t < KK)
        out[(size_t)BB * KK * FDIM + b * KK + t] = (float)sel_idx[t];
}

extern "C" void kernel_launch(void* const* d_in, const int* in_sizes, int n_in,
                              void* d_out, int out_size)
{
    const float* x  = (const float*)d_in[0];   // (B, N, FDIM) f32
    const float* hf = (const float*)d_in[1];   // (B, N, L, DH) f32
    const float* he = (const float*)d_in[2];   // (B, N, FDIM) f32
    float* out = (float*)d_out;

    unsigned long long* cand;
    cudaGetSymbolAddress((void**)&cand, g_cand);

    fused_kernel<<<BB * CHUNKS, APB>>>(x, hf, he, cand, out);
}